// round 4
// baseline (speedup 1.0000x reference)
#include <cuda_runtime.h>

#define NN 100000
#define NE 1600000
#define DD 128

// ---------------- scratch (device globals; no allocation allowed) ----------
__device__ int g_deg[NN];
__device__ int g_rowptr[NN];
__device__ int g_cursor[NN];
__device__ int g_eidx[NE];
__device__ int g_bsums[128];
__device__ __align__(16) float g_Wcat[256 * 128];          // [k][j], k-major
__device__ __align__(16) float g_X[(size_t)NN * 256];      // [n][0:128]=neigh, [128:256]=edge

// ---------------- f32x2 packed-FMA helpers ---------------------------------
__device__ __forceinline__ unsigned long long pk2(float x, float y) {
    unsigned long long r;
    asm("mov.b64 %0, {%1, %2};" : "=l"(r) : "f"(x), "f"(y));
    return r;
}
__device__ __forceinline__ void upk2(unsigned long long v, float& x, float& y) {
    asm("mov.b64 {%0, %1}, %2;" : "=f"(x), "=f"(y) : "l"(v));
}
__device__ __forceinline__ void fma2(unsigned long long& d, unsigned long long a,
                                     unsigned long long b) {
    asm("fma.rn.f32x2 %0, %1, %2, %0;" : "+l"(d) : "l"(a), "l"(b));
}

// ---------------- K0: zero deg + build Wcat = [Wn^T ; We^T] ----------------
__global__ void k_init(const float* __restrict__ Wn, const float* __restrict__ We) {
    int stride = gridDim.x * blockDim.x;
    int i0 = blockIdx.x * blockDim.x + threadIdx.x;
    for (int j = i0; j < NN; j += stride) g_deg[j] = 0;
    for (int j = i0; j < 256 * 128; j += stride) {
        int k = j >> 7, c = j & 127;
        // out[n,c] = sum_k X[n,k] * Wcat[k,c];  Wn stored [c][k] row-major (W_neigh[j,k])
        g_Wcat[j] = (k < 128) ? Wn[c * 128 + k] : We[c * 128 + (k - 128)];
    }
}

// ---------------- K1: degree histogram -------------------------------------
__global__ void k_deg(const int* __restrict__ dst) {
    int stride = gridDim.x * blockDim.x;
    for (int e = blockIdx.x * blockDim.x + threadIdx.x; e < NE; e += stride)
        atomicAdd(&g_deg[dst[e]], 1);
}

// ---------------- K2a: per-block exclusive scan ----------------------------
__global__ void k_scan1() {
    __shared__ int sh[1024];
    int gid = blockIdx.x * 1024 + threadIdx.x;
    int v = (gid < NN) ? g_deg[gid] : 0;
    sh[threadIdx.x] = v;
    __syncthreads();
    for (int off = 1; off < 1024; off <<= 1) {
        int t = (threadIdx.x >= (unsigned)off) ? sh[threadIdx.x - off] : 0;
        __syncthreads();
        sh[threadIdx.x] += t;
        __syncthreads();
    }
    if (gid < NN) g_rowptr[gid] = sh[threadIdx.x] - v;  // exclusive
    if (threadIdx.x == 1023) g_bsums[blockIdx.x] = sh[1023];
}

// ---------------- K2b: scan block sums (tiny) ------------------------------
__global__ void k_scan2(int nb) {
    __shared__ int sh[128];
    if (threadIdx.x < nb) sh[threadIdx.x] = g_bsums[threadIdx.x];
    __syncthreads();
    if (threadIdx.x == 0) {
        int acc = 0;
        for (int i = 0; i < nb; i++) { int t = sh[i]; sh[i] = acc; acc += t; }
    }
    __syncthreads();
    if (threadIdx.x < nb) g_bsums[threadIdx.x] = sh[threadIdx.x];
}

// ---------------- K2c: add block offsets, init cursors ---------------------
__global__ void k_addoff() {
    int gid = blockIdx.x * 1024 + threadIdx.x;
    if (gid < NN) {
        int v = g_rowptr[gid] + g_bsums[blockIdx.x];
        g_rowptr[gid] = v;
        g_cursor[gid] = v;
    }
}

// ---------------- K3: fill CSR edge lists ----------------------------------
__global__ void k_fill(const int* __restrict__ dst) {
    int stride = gridDim.x * blockDim.x;
    for (int e = blockIdx.x * blockDim.x + threadIdx.x; e < NE; e += stride) {
        int d = dst[e];
        int p = atomicAdd(&g_cursor[d], 1);
        g_eidx[p] = e;
    }
}

// ---------------- K4: gather-side aggregation (warp per node) --------------
__global__ void __launch_bounds__(256) k_agg(const float* __restrict__ nfeat,
                                             const float* __restrict__ efeat,
                                             const float* __restrict__ ew,
                                             const int* __restrict__ src) {
    int n = (blockIdx.x * 256 + threadIdx.x) >> 5;
    if (n >= NN) return;
    int lane = threadIdx.x & 31;
    int c = lane * 4;

    int start = g_rowptr[n];
    int cnt = g_deg[n];

    float4 sf = *(const float4*)&nfeat[(size_t)n * DD + c];
    float an0 = 2.f * sf.x, an1 = 2.f * sf.y, an2 = 2.f * sf.z, an3 = 2.f * sf.w;
    float ae0 = 0.f, ae1 = 0.f, ae2 = 0.f, ae3 = 0.f;

    int i = 0;
    for (; i + 2 <= cnt; i += 2) {
        int e0 = g_eidx[start + i];
        int e1 = g_eidx[start + i + 1];
        int s0 = __ldg(&src[e0]);
        int s1 = __ldg(&src[e1]);
        float w0 = __ldg(&ew[e0]);
        float w1 = __ldg(&ew[e1]);
        float4 v0 = *(const float4*)&nfeat[(size_t)s0 * DD + c];
        float4 u0 = *(const float4*)&efeat[(size_t)e0 * DD + c];
        float4 v1 = *(const float4*)&nfeat[(size_t)s1 * DD + c];
        float4 u1 = *(const float4*)&efeat[(size_t)e1 * DD + c];
        an0 += v0.x * w0 + v1.x * w1;
        an1 += v0.y * w0 + v1.y * w1;
        an2 += v0.z * w0 + v1.z * w1;
        an3 += v0.w * w0 + v1.w * w1;
        ae0 += u0.x + u1.x;
        ae1 += u0.y + u1.y;
        ae2 += u0.z + u1.z;
        ae3 += u0.w + u1.w;
    }
    if (i < cnt) {
        int e0 = g_eidx[start + i];
        int s0 = __ldg(&src[e0]);
        float w0 = __ldg(&ew[e0]);
        float4 v0 = *(const float4*)&nfeat[(size_t)s0 * DD + c];
        float4 u0 = *(const float4*)&efeat[(size_t)e0 * DD + c];
        an0 += v0.x * w0; an1 += v0.y * w0; an2 += v0.z * w0; an3 += v0.w * w0;
        ae0 += u0.x; ae1 += u0.y; ae2 += u0.z; ae3 += u0.w;
    }

    float invd = 1.f / (float)(cnt + 1);
    float inve = (cnt > 0) ? 1.f / (float)cnt : 0.f;
    *(float4*)&g_X[(size_t)n * 256 + c] =
        make_float4(an0 * invd, an1 * invd, an2 * invd, an3 * invd);
    *(float4*)&g_X[(size_t)n * 256 + 128 + c] =
        make_float4(ae0 * inve, ae1 * inve, ae2 * inve, ae3 * inve);
}

// ---------------- K5: fused GEMM  out = X @ Wcat + bias --------------------
// block tile: 64 rows x 128 cols; thread tile: 4 rows x 8 cols (f32x2 pairs)
__global__ void __launch_bounds__(256) k_gemm(const float* __restrict__ bn,
                                              const float* __restrict__ be,
                                              float* __restrict__ out) {
    __shared__ float Xs[64][33];
    __shared__ __align__(16) float Ws[32][128];

    int tid = threadIdx.x;
    int rowbase = blockIdx.x * 64;
    int row0 = (tid >> 4) * 4;
    int col0 = (tid & 15) * 8;

    unsigned long long acc[4][4];
#pragma unroll
    for (int i = 0; i < 4; i++)
#pragma unroll
        for (int p = 0; p < 4; p++) acc[i][p] = pk2(0.f, 0.f);

    float bnr[8], ber[8];
#pragma unroll
    for (int j = 0; j < 8; j++) {
        bnr[j] = __ldg(&bn[col0 + j]);
        ber[j] = __ldg(&be[col0 + j]);
    }

    for (int kc = 0; kc < 256; kc += 32) {
        // stage X tile [64 rows x 32 k] (padded to kill bank conflicts)
#pragma unroll
        for (int t = 0; t < 2; t++) {
            int fid = tid + t * 256;
            int r = fid >> 3, kq = fid & 7;
            int gr = rowbase + r;
            float4 xv = make_float4(0.f, 0.f, 0.f, 0.f);
            if (gr < NN) xv = *(const float4*)&g_X[(size_t)gr * 256 + kc + kq * 4];
            Xs[r][kq * 4 + 0] = xv.x;
            Xs[r][kq * 4 + 1] = xv.y;
            Xs[r][kq * 4 + 2] = xv.z;
            Xs[r][kq * 4 + 3] = xv.w;
        }
        // stage W tile [32 k x 128 cols]
#pragma unroll
        for (int t = 0; t < 4; t++) {
            int wf = tid + t * 256;
            int kr = wf >> 5, c4 = wf & 31;
            *(float4*)&Ws[kr][c4 * 4] =
                *(const float4*)&g_Wcat[(size_t)(kc + kr) * 128 + c4 * 4];
        }
        __syncthreads();

#pragma unroll 8
        for (int k = 0; k < 32; k++) {
            float4 wA = *(const float4*)&Ws[k][col0];
            float4 wB = *(const float4*)&Ws[k][col0 + 4];
            unsigned long long b0 = pk2(wA.x, wA.y);
            unsigned long long b1 = pk2(wA.z, wA.w);
            unsigned long long b2 = pk2(wB.x, wB.y);
            unsigned long long b3 = pk2(wB.z, wB.w);
#pragma unroll
            for (int i = 0; i < 4; i++) {
                float x = Xs[row0 + i][k];
                unsigned long long a = pk2(x, x);
                fma2(acc[i][0], a, b0);
                fma2(acc[i][1], a, b1);
                fma2(acc[i][2], a, b2);
                fma2(acc[i][3], a, b3);
            }
        }
        __syncthreads();
    }

    // epilogue: add b_neigh + 1[deg>0]*b_edge, store
#pragma unroll
    for (int i = 0; i < 4; i++) {
        int n = rowbase + row0 + i;
        if (n >= NN) continue;
        float f = (g_deg[n] > 0) ? 1.f : 0.f;
        float o[8];
#pragma unroll
        for (int p = 0; p < 4; p++) upk2(acc[i][p], o[2 * p], o[2 * p + 1]);
#pragma unroll
        for (int j = 0; j < 8; j++) o[j] += bnr[j] + f * ber[j];
        *(float4*)&out[(size_t)n * DD + col0] = make_float4(o[0], o[1], o[2], o[3]);
        *(float4*)&out[(size_t)n * DD + col0 + 4] = make_float4(o[4], o[5], o[6], o[7]);
    }
}

// ---------------- launch ----------------------------------------------------
extern "C" void kernel_launch(void* const* d_in, const int* in_sizes, int n_in,
                              void* d_out, int out_size) {
    const float* nfeat = (const float*)d_in[0];
    const float* efeat = (const float*)d_in[1];
    const float* ew    = (const float*)d_in[2];
    const float* Wn    = (const float*)d_in[3];
    const float* bn    = (const float*)d_in[4];
    const float* We    = (const float*)d_in[5];
    const float* be    = (const float*)d_in[6];
    const int*   src   = (const int*)d_in[7];
    const int*   dst   = (const int*)d_in[8];
    float* out = (float*)d_out;

    const int nscan = (NN + 1023) / 1024;  // 98

    k_init<<<400, 256>>>(Wn, We);
    k_deg<<<(NE + 255) / 256, 256>>>(dst);
    k_scan1<<<nscan, 1024>>>();
    k_scan2<<<1, 128>>>(nscan);
    k_addoff<<<nscan, 1024>>>();
    k_fill<<<(NE + 255) / 256, 256>>>(dst);
    k_agg<<<(NN * 32 + 255) / 256, 256>>>(nfeat, efeat, ew, src);
    k_gemm<<<(NN + 63) / 64, 256>>>(bn, be, out);
}

// round 7
// speedup vs baseline: 1.5044x; 1.5044x over previous
#include <cuda_runtime.h>
#include <cuda_bf16.h>

#define NN 100000
#define NE 1600000
#define DD 128

// ---------------- scratch (device globals; no allocation allowed) ----------
__device__ int g_deg[NN];
__device__ int g_rowptr[NN];
__device__ int g_cursor[NN];
__device__ int g_bsums[128];
__device__ __align__(16) int4 g_rec[NE];                       // {src, w_bits, e, 0} per CSR slot
__device__ __align__(16) __nv_bfloat16 g_Wh[128 * 256];        // W split hi, [n][k] k-contig
__device__ __align__(16) __nv_bfloat16 g_Wl[128 * 256];        // W split lo
__device__ __align__(16) __nv_bfloat16 g_Xh[(size_t)NN * 256]; // X split hi, [n][k]
__device__ __align__(16) __nv_bfloat16 g_Xl[(size_t)NN * 256]; // X split lo

// ---------------- helpers ---------------------------------------------------
__device__ __forceinline__ unsigned pack_bf2(__nv_bfloat16 a, __nv_bfloat16 b) {
    return ((unsigned)__bfloat16_as_ushort(b) << 16) | (unsigned)__bfloat16_as_ushort(a);
}

__device__ __forceinline__ void mma_bf16(float* c, unsigned a0, unsigned a1, unsigned a2,
                                         unsigned a3, unsigned b0, unsigned b1) {
    asm volatile(
        "mma.sync.aligned.m16n8k16.row.col.f32.bf16.bf16.f32 "
        "{%0,%1,%2,%3}, {%4,%5,%6,%7}, {%8,%9}, {%0,%1,%2,%3};"
        : "+f"(c[0]), "+f"(c[1]), "+f"(c[2]), "+f"(c[3])
        : "r"(a0), "r"(a1), "r"(a2), "r"(a3), "r"(b0), "r"(b1));
}

// ---------------- K0: zero deg + build split W = [Wn | We] rows -------------
// out[n,c] = sum_k X[n,k] * W[c,k]  with W[c, 0:128] = Wn row c, W[c,128:256] = We row c
__global__ void k_init(const float* __restrict__ Wn, const float* __restrict__ We) {
    int stride = gridDim.x * blockDim.x;
    int i0 = blockIdx.x * blockDim.x + threadIdx.x;
    for (int j = i0; j < NN; j += stride) g_deg[j] = 0;
    for (int j = i0; j < 128 * 256; j += stride) {
        int c = j >> 8, k = j & 255;
        float w = (k < 128) ? Wn[c * 128 + k] : We[c * 128 + (k - 128)];
        __nv_bfloat16 hi = __float2bfloat16_rn(w);
        __nv_bfloat16 lo = __float2bfloat16_rn(w - __bfloat162float(hi));
        g_Wh[j] = hi;
        g_Wl[j] = lo;
    }
}

// ---------------- K1: degree histogram --------------------------------------
__global__ void k_deg(const int* __restrict__ dst) {
    int stride = gridDim.x * blockDim.x;
    for (int e = blockIdx.x * blockDim.x + threadIdx.x; e < NE; e += stride)
        atomicAdd(&g_deg[dst[e]], 1);
}

// ---------------- K2a: per-block exclusive scan -----------------------------
__global__ void k_scan1() {
    __shared__ int sh[1024];
    int gid = blockIdx.x * 1024 + threadIdx.x;
    int v = (gid < NN) ? g_deg[gid] : 0;
    sh[threadIdx.x] = v;
    __syncthreads();
    for (int off = 1; off < 1024; off <<= 1) {
        int t = (threadIdx.x >= (unsigned)off) ? sh[threadIdx.x - off] : 0;
        __syncthreads();
        sh[threadIdx.x] += t;
        __syncthreads();
    }
    if (gid < NN) g_rowptr[gid] = sh[threadIdx.x] - v;  // exclusive
    if (threadIdx.x == 1023) g_bsums[blockIdx.x] = sh[1023];
}

// ---------------- K2b: scan block sums (tiny) -------------------------------
__global__ void k_scan2(int nb) {
    __shared__ int sh[128];
    if (threadIdx.x < nb) sh[threadIdx.x] = g_bsums[threadIdx.x];
    __syncthreads();
    if (threadIdx.x == 0) {
        int acc = 0;
        for (int i = 0; i < nb; i++) { int t = sh[i]; sh[i] = acc; acc += t; }
    }
    __syncthreads();
    if (threadIdx.x < nb) g_bsums[threadIdx.x] = sh[threadIdx.x];
}

// ---------------- K2c: add block offsets, init cursors ----------------------
__global__ void k_addoff() {
    int gid = blockIdx.x * 1024 + threadIdx.x;
    if (gid < NN) {
        int v = g_rowptr[gid] + g_bsums[blockIdx.x];
        g_rowptr[gid] = v;
        g_cursor[gid] = v;
    }
}

// ---------------- K3: fill CSR with packed (src, w, e) records --------------
__global__ void k_fill(const int* __restrict__ dst, const int* __restrict__ src,
                       const float* __restrict__ ew) {
    int stride = gridDim.x * blockDim.x;
    for (int e = blockIdx.x * blockDim.x + threadIdx.x; e < NE; e += stride) {
        int d = dst[e];
        int p = atomicAdd(&g_cursor[d], 1);
        g_rec[p] = make_int4(src[e], __float_as_int(ew[e]), e, 0);
    }
}

// ---------------- K4: gather aggregation (warp per node), bf16-split X ------
__global__ void __launch_bounds__(256) k_agg(const float* __restrict__ nfeat,
                                             const float* __restrict__ efeat) {
    int n = (blockIdx.x * 256 + threadIdx.x) >> 5;
    if (n >= NN) return;
    int lane = threadIdx.x & 31;
    int c = lane * 4;

    int start = g_rowptr[n];
    int cnt = g_deg[n];

    float4 sf = *(const float4*)&nfeat[(size_t)n * DD + c];
    float an0 = 2.f * sf.x, an1 = 2.f * sf.y, an2 = 2.f * sf.z, an3 = 2.f * sf.w;
    float ae0 = 0.f, ae1 = 0.f, ae2 = 0.f, ae3 = 0.f;

    int i = 0;
    for (; i + 4 <= cnt; i += 4) {
        // uniform per-warp record loads (broadcast), then batch feature loads -> high MLP
        int4 q0 = __ldg(&g_rec[start + i]);
        int4 q1 = __ldg(&g_rec[start + i + 1]);
        int4 q2 = __ldg(&g_rec[start + i + 2]);
        int4 q3 = __ldg(&g_rec[start + i + 3]);
        float4 v0 = *(const float4*)&nfeat[(size_t)q0.x * DD + c];
        float4 v1 = *(const float4*)&nfeat[(size_t)q1.x * DD + c];
        float4 v2 = *(const float4*)&nfeat[(size_t)q2.x * DD + c];
        float4 v3 = *(const float4*)&nfeat[(size_t)q3.x * DD + c];
        float4 u0 = __ldcs((const float4*)&efeat[(size_t)q0.z * DD + c]);
        float4 u1 = __ldcs((const float4*)&efeat[(size_t)q1.z * DD + c]);
        float4 u2 = __ldcs((const float4*)&efeat[(size_t)q2.z * DD + c]);
        float4 u3 = __ldcs((const float4*)&efeat[(size_t)q3.z * DD + c]);
        float w0 = __int_as_float(q0.y), w1 = __int_as_float(q1.y);
        float w2 = __int_as_float(q2.y), w3 = __int_as_float(q3.y);
        an0 += v0.x * w0 + v1.x * w1 + v2.x * w2 + v3.x * w3;
        an1 += v0.y * w0 + v1.y * w1 + v2.y * w2 + v3.y * w3;
        an2 += v0.z * w0 + v1.z * w1 + v2.z * w2 + v3.z * w3;
        an3 += v0.w * w0 + v1.w * w1 + v2.w * w2 + v3.w * w3;
        ae0 += (u0.x + u1.x) + (u2.x + u3.x);
        ae1 += (u0.y + u1.y) + (u2.y + u3.y);
        ae2 += (u0.z + u1.z) + (u2.z + u3.z);
        ae3 += (u0.w + u1.w) + (u2.w + u3.w);
    }
    for (; i < cnt; i++) {
        int4 q0 = __ldg(&g_rec[start + i]);
        float4 v0 = *(const float4*)&nfeat[(size_t)q0.x * DD + c];
        float4 u0 = __ldcs((const float4*)&efeat[(size_t)q0.z * DD + c]);
        float w0 = __int_as_float(q0.y);
        an0 += v0.x * w0; an1 += v0.y * w0; an2 += v0.z * w0; an3 += v0.w * w0;
        ae0 += u0.x; ae1 += u0.y; ae2 += u0.z; ae3 += u0.w;
    }

    float invd = 1.f / (float)(cnt + 1);
    float inve = (cnt > 0) ? 1.f / (float)cnt : 0.f;
    float xv[8] = {an0 * invd, an1 * invd, an2 * invd, an3 * invd,
                   ae0 * inve, ae1 * inve, ae2 * inve, ae3 * inve};

    // split to bf16 hi/lo; neigh part at k=c, edge part at k=128+c
    unsigned hp[4], lp[4];
#pragma unroll
    for (int p = 0; p < 4; p++) {
        __nv_bfloat16 h0 = __float2bfloat16_rn(xv[2 * p]);
        __nv_bfloat16 h1 = __float2bfloat16_rn(xv[2 * p + 1]);
        __nv_bfloat16 l0 = __float2bfloat16_rn(xv[2 * p] - __bfloat162float(h0));
        __nv_bfloat16 l1 = __float2bfloat16_rn(xv[2 * p + 1] - __bfloat162float(h1));
        hp[p] = pack_bf2(h0, h1);
        lp[p] = pack_bf2(l0, l1);
    }
    size_t base = (size_t)n * 256 + c;
    *(uint2*)&g_Xh[base]       = make_uint2(hp[0], hp[1]);
    *(uint2*)&g_Xh[base + 128] = make_uint2(hp[2], hp[3]);
    *(uint2*)&g_Xl[base]       = make_uint2(lp[0], lp[1]);
    *(uint2*)&g_Xl[base + 128] = make_uint2(lp[2], lp[3]);
}

// ---------------- K5: tensor-core GEMM, bf16x3 split ------------------------
// out[100000,128] = Xh*Wh + Xh*Wl + Xl*Wh + bias ; CTA tile 128x128, K=256
__global__ void __launch_bounds__(256, 2) k_gemm_tc(const float* __restrict__ bn,
                                                    const float* __restrict__ be,
                                                    float* __restrict__ out) {
    __shared__ __nv_bfloat16 Xh[128][34], Xl[128][34], Wh[128][34], Wl[128][34];

    int tid = threadIdx.x;
    int lane = tid & 31, wid = tid >> 5;
    int g = lane >> 2, t = lane & 3;
    int mw = (wid >> 1) * 32, nw = (wid & 1) * 64;
    int rowbase = blockIdx.x * 128;

    float acc[2][8][4];
#pragma unroll
    for (int mt = 0; mt < 2; mt++)
#pragma unroll
        for (int nt = 0; nt < 8; nt++)
#pragma unroll
            for (int p = 0; p < 4; p++) acc[mt][nt][p] = 0.f;

    int r = tid >> 1;
    int seg = (tid & 1) * 16;

    for (int kc = 0; kc < 256; kc += 32) {
        // load stage data to regs first
        uint4 xh0, xh1, xl0, xl1, wh0, wh1, wl0, wl1;
        size_t gx = (size_t)(rowbase + r) * 256 + kc + seg;
        if (rowbase + r < NN) {
            xh0 = *(const uint4*)&g_Xh[gx];
            xh1 = *(const uint4*)&g_Xh[gx + 8];
            xl0 = *(const uint4*)&g_Xl[gx];
            xl1 = *(const uint4*)&g_Xl[gx + 8];
        } else {
            xh0 = xh1 = xl0 = xl1 = make_uint4(0, 0, 0, 0);
        }
        size_t gw = (size_t)r * 256 + kc + seg;
        wh0 = *(const uint4*)&g_Wh[gw];
        wh1 = *(const uint4*)&g_Wh[gw + 8];
        wl0 = *(const uint4*)&g_Wl[gw];
        wl1 = *(const uint4*)&g_Wl[gw + 8];

        __syncthreads();  // previous tile fully consumed
        {
            unsigned* dx = (unsigned*)&Xh[r][seg];
            dx[0] = xh0.x; dx[1] = xh0.y; dx[2] = xh0.z; dx[3] = xh0.w;
            dx[4] = xh1.x; dx[5] = xh1.y; dx[6] = xh1.z; dx[7] = xh1.w;
            unsigned* dl = (unsigned*)&Xl[r][seg];
            dl[0] = xl0.x; dl[1] = xl0.y; dl[2] = xl0.z; dl[3] = xl0.w;
            dl[4] = xl1.x; dl[5] = xl1.y; dl[6] = xl1.z; dl[7] = xl1.w;
            unsigned* dw = (unsigned*)&Wh[r][seg];
            dw[0] = wh0.x; dw[1] = wh0.y; dw[2] = wh0.z; dw[3] = wh0.w;
            dw[4] = wh1.x; dw[5] = wh1.y; dw[6] = wh1.z; dw[7] = wh1.w;
            unsigned* dv = (unsigned*)&Wl[r][seg];
            dv[0] = wl0.x; dv[1] = wl0.y; dv[2] = wl0.z; dv[3] = wl0.w;
            dv[4] = wl1.x; dv[5] = wl1.y; dv[6] = wl1.z; dv[7] = wl1.w;
        }
        __syncthreads();

#pragma unroll
        for (int kk = 0; kk < 32; kk += 16) {
            // A fragments for both 16-row tiles (hi and lo)
            unsigned ah[2][4], al[2][4];
#pragma unroll
            for (int mt = 0; mt < 2; mt++) {
                int rb = mw + mt * 16;
                ah[mt][0] = *(const unsigned*)&Xh[rb + g][kk + t * 2];
                ah[mt][1] = *(const unsigned*)&Xh[rb + g + 8][kk + t * 2];
                ah[mt][2] = *(const unsigned*)&Xh[rb + g][kk + t * 2 + 8];
                ah[mt][3] = *(const unsigned*)&Xh[rb + g + 8][kk + t * 2 + 8];
                al[mt][0] = *(const unsigned*)&Xl[rb + g][kk + t * 2];
                al[mt][1] = *(const unsigned*)&Xl[rb + g + 8][kk + t * 2];
                al[mt][2] = *(const unsigned*)&Xl[rb + g][kk + t * 2 + 8];
                al[mt][3] = *(const unsigned*)&Xl[rb + g + 8][kk + t * 2 + 8];
            }
#pragma unroll
            for (int nt = 0; nt < 8; nt++) {
                int nb = nw + nt * 8;
                unsigned bh0 = *(const unsigned*)&Wh[nb + g][kk + t * 2];
                unsigned bh1 = *(const unsigned*)&Wh[nb + g][kk + t * 2 + 8];
                unsigned bl0 = *(const unsigned*)&Wl[nb + g][kk + t * 2];
                unsigned bl1 = *(const unsigned*)&Wl[nb + g][kk + t * 2 + 8];
#pragma unroll
                for (int mt = 0; mt < 2; mt++) {
                    mma_bf16(acc[mt][nt], ah[mt][0], ah[mt][1], ah[mt][2], ah[mt][3], bh0, bh1);
                    mma_bf16(acc[mt][nt], ah[mt][0], ah[mt][1], ah[mt][2], ah[mt][3], bl0, bl1);
                    mma_bf16(acc[mt][nt], al[mt][0], al[mt][1], al[mt][2], al[mt][3], bh0, bh1);
                }
            }
        }
        __syncthreads();
    }

    // epilogue: bias + deg-gated edge bias, fp32 stores
#pragma unroll
    for (int nt = 0; nt < 8; nt++) {
        int col = nw + nt * 8 + t * 2;
        float bn0 = __ldg(&bn[col]), bn1 = __ldg(&bn[col + 1]);
        float be0 = __ldg(&be[col]), be1 = __ldg(&be[col + 1]);
#pragma unroll
        for (int mt = 0; mt < 2; mt++) {
            int m0 = rowbase + mw + mt * 16 + g;
            if (m0 < NN) {
                float f = (g_deg[m0] > 0) ? 1.f : 0.f;
                *(float2*)&out[(size_t)m0 * DD + col] =
                    make_float2(acc[mt][nt][0] + bn0 + f * be0,
                                acc[mt][nt][1] + bn1 + f * be1);
            }
            int m1 = m0 + 8;
            if (m1 < NN) {
                float f = (g_deg[m1] > 0) ? 1.f : 0.f;
                *(float2*)&out[(size_t)m1 * DD + col] =
                    make_float2(acc[mt][nt][2] + bn0 + f * be0,
                                acc[mt][nt][3] + bn1 + f * be1);
            }
        }
    }
}

// ---------------- launch ----------------------------------------------------
extern "C" void kernel_launch(void* const* d_in, const int* in_sizes, int n_in,
                              void* d_out, int out_size) {
    const float* nfeat = (const float*)d_in[0];
    const float* efeat = (const float*)d_in[1];
    const float* ew    = (const float*)d_in[2];
    const float* Wn    = (const float*)d_in[3];
    const float* bn    = (const float*)d_in[4];
    const float* We    = (const float*)d_in[5];
    const float* be    = (const float*)d_in[6];
    const int*   src   = (const int*)d_in[7];
    const int*   dst   = (const int*)d_in[8];
    float* out = (float*)d_out;

    const int nscan = (NN + 1023) / 1024;  // 98

    k_init<<<400, 256>>>(Wn, We);
    k_deg<<<(NE + 255) / 256, 256>>>(dst);
    k_scan1<<<nscan, 1024>>>();
    k_scan2<<<1, 128>>>(nscan);
    k_addoff<<<nscan, 1024>>>();
    k_fill<<<(NE + 255) / 256, 256>>>(dst, src, ew);
    k_agg<<<(NN * 32 + 255) / 256, 256>>>(nfeat, efeat);
    k_gemm_tc<<<(NN + 127) / 128, 256>>>(bn, be, out);
}

// round 9
// speedup vs baseline: 1.6265x; 1.0812x over previous
#include <cuda_runtime.h>
#include <cuda_bf16.h>

#define NN 100000
#define NE 1600000
#define DD 128

// ---------------- scratch (device globals; no allocation allowed) ----------
__device__ int g_deg[NN];
__device__ int g_rowptr[NN];
__device__ int g_cursor[NN];
__device__ int g_bsums[128];
__device__ __align__(16) int4 g_rec[NE];                       // {src, w_bits, e, 0} per CSR slot
__device__ __align__(16) __nv_bfloat16 g_Wh[128 * 256];        // W split hi, [c][k] k-contig
__device__ __align__(16) __nv_bfloat16 g_Wl[128 * 256];        // W split lo
__device__ __align__(16) __nv_bfloat16 g_Xh[(size_t)NN * 256]; // X split hi, [n][k]
__device__ __align__(16) __nv_bfloat16 g_Xl[(size_t)NN * 256]; // X split lo

// ---------------- helpers ---------------------------------------------------
__device__ __forceinline__ unsigned pack_bf2(__nv_bfloat16 a, __nv_bfloat16 b) {
    return ((unsigned)__bfloat16_as_ushort(b) << 16) | (unsigned)__bfloat16_as_ushort(a);
}

__device__ __forceinline__ void mma_bf16(float* c, unsigned a0, unsigned a1, unsigned a2,
                                         unsigned a3, unsigned b0, unsigned b1) {
    asm volatile(
        "mma.sync.aligned.m16n8k16.row.col.f32.bf16.bf16.f32 "
        "{%0,%1,%2,%3}, {%4,%5,%6,%7}, {%8,%9}, {%0,%1,%2,%3};"
        : "+f"(c[0]), "+f"(c[1]), "+f"(c[2]), "+f"(c[3])
        : "r"(a0), "r"(a1), "r"(a2), "r"(a3), "r"(b0), "r"(b1));
}

// cp.async 16B, zero-fill when pred==false (src-size 0)
__device__ __forceinline__ void cp16(void* dst_smem, const void* src, bool pred) {
    unsigned d = (unsigned)__cvta_generic_to_shared(dst_smem);
    int sz = pred ? 16 : 0;
    asm volatile("cp.async.cg.shared.global [%0], [%1], 16, %2;\n"
                 :: "r"(d), "l"(src), "r"(sz));
}
__device__ __forceinline__ void cp_commit() {
    asm volatile("cp.async.commit_group;\n" ::: "memory");
}
template <int N>
__device__ __forceinline__ void cp_wait() {
    asm volatile("cp.async.wait_group %0;\n" :: "n"(N) : "memory");
}

// ---------------- K0: zero deg + build split W = [Wn | We] rows -------------
// out[n,c] = sum_k X[n,k] * W[c,k];  W[c,0:128]=Wn row c, W[c,128:256]=We row c
__global__ void k_init(const float* __restrict__ Wn, const float* __restrict__ We) {
    int stride = gridDim.x * blockDim.x;
    int i0 = blockIdx.x * blockDim.x + threadIdx.x;
    for (int j = i0; j < NN; j += stride) g_deg[j] = 0;
    for (int j = i0; j < 128 * 256; j += stride) {
        int c = j >> 8, k = j & 255;
        float w = (k < 128) ? Wn[c * 128 + k] : We[c * 128 + (k - 128)];
        __nv_bfloat16 hi = __float2bfloat16_rn(w);
        __nv_bfloat16 lo = __float2bfloat16_rn(w - __bfloat162float(hi));
        g_Wh[j] = hi;
        g_Wl[j] = lo;
    }
}

// ---------------- K1: degree histogram --------------------------------------
__global__ void k_deg(const int* __restrict__ dst) {
    int stride = gridDim.x * blockDim.x;
    for (int e = blockIdx.x * blockDim.x + threadIdx.x; e < NE; e += stride)
        atomicAdd(&g_deg[dst[e]], 1);
}

// ---------------- K2a: per-block exclusive scan -----------------------------
__global__ void k_scan1() {
    __shared__ int sh[1024];
    int gid = blockIdx.x * 1024 + threadIdx.x;
    int v = (gid < NN) ? g_deg[gid] : 0;
    sh[threadIdx.x] = v;
    __syncthreads();
    for (int off = 1; off < 1024; off <<= 1) {
        int t = (threadIdx.x >= (unsigned)off) ? sh[threadIdx.x - off] : 0;
        __syncthreads();
        sh[threadIdx.x] += t;
        __syncthreads();
    }
    if (gid < NN) g_rowptr[gid] = sh[threadIdx.x] - v;  // exclusive within block
    if (threadIdx.x == 1023) g_bsums[blockIdx.x] = sh[1023];
}

// ---------------- K2b: add block offsets (self-computed prefix), init cursors
__global__ void k_addoff() {
    __shared__ int off;
    if (threadIdx.x < 32) {
        int lane = threadIdx.x;
        int acc = 0;
        for (int b = lane; b < blockIdx.x; b += 32) acc += g_bsums[b];
#pragma unroll
        for (int o = 16; o; o >>= 1) acc += __shfl_xor_sync(0xffffffffu, acc, o);
        if (lane == 0) off = acc;
    }
    __syncthreads();
    int gid = blockIdx.x * 1024 + threadIdx.x;
    if (gid < NN) {
        int v = g_rowptr[gid] + off;
        g_rowptr[gid] = v;
        g_cursor[gid] = v;
    }
}

// ---------------- K3: fill CSR with packed (src, w, e) records --------------
__global__ void k_fill(const int* __restrict__ dst, const int* __restrict__ src,
                       const float* __restrict__ ew) {
    int stride = gridDim.x * blockDim.x;
    for (int e = blockIdx.x * blockDim.x + threadIdx.x; e < NE; e += stride) {
        int d = dst[e];
        int p = atomicAdd(&g_cursor[d], 1);
        __stcs(&g_rec[p], make_int4(src[e], __float_as_int(ew[e]), e, 0));
    }
}

// ---------------- K4: gather aggregation (warp per node), rec prefetch ------
__global__ void __launch_bounds__(256) k_agg(const float* __restrict__ nfeat,
                                             const float* __restrict__ efeat) {
    int n = (blockIdx.x * 256 + threadIdx.x) >> 5;
    if (n >= NN) return;
    int lane = threadIdx.x & 31;
    int c = lane * 4;

    int start = g_rowptr[n];
    int cnt = g_deg[n];

    float4 sf = *(const float4*)&nfeat[(size_t)n * DD + c];
    float an0 = 2.f * sf.x, an1 = 2.f * sf.y, an2 = 2.f * sf.z, an3 = 2.f * sf.w;
    float ae0 = 0.f, ae1 = 0.f, ae2 = 0.f, ae3 = 0.f;

    int i = 0;
    if (cnt >= 4) {
        int4 q0 = __ldcs(&g_rec[start + 0]);
        int4 q1 = __ldcs(&g_rec[start + 1]);
        int4 q2 = __ldcs(&g_rec[start + 2]);
        int4 q3 = __ldcs(&g_rec[start + 3]);
        for (; i + 4 <= cnt;) {
            // feature loads for current recs (8 loads in flight)
            float4 v0 = __ldg((const float4*)&nfeat[(size_t)q0.x * DD + c]);
            float4 v1 = __ldg((const float4*)&nfeat[(size_t)q1.x * DD + c]);
            float4 v2 = __ldg((const float4*)&nfeat[(size_t)q2.x * DD + c]);
            float4 v3 = __ldg((const float4*)&nfeat[(size_t)q3.x * DD + c]);
            float4 u0 = __ldcs((const float4*)&efeat[(size_t)q0.z * DD + c]);
            float4 u1 = __ldcs((const float4*)&efeat[(size_t)q1.z * DD + c]);
            float4 u2 = __ldcs((const float4*)&efeat[(size_t)q2.z * DD + c]);
            float4 u3 = __ldcs((const float4*)&efeat[(size_t)q3.z * DD + c]);
            float w0 = __int_as_float(q0.y), w1 = __int_as_float(q1.y);
            float w2 = __int_as_float(q2.y), w3 = __int_as_float(q3.y);

            // prefetch next 4 records while features are in flight
            int nx = i + 4;
            int4 p0 = q0, p1 = q1, p2 = q2, p3 = q3;
            if (nx + 4 <= cnt) {
                p0 = __ldcs(&g_rec[start + nx + 0]);
                p1 = __ldcs(&g_rec[start + nx + 1]);
                p2 = __ldcs(&g_rec[start + nx + 2]);
                p3 = __ldcs(&g_rec[start + nx + 3]);
            }

            an0 += v0.x * w0 + v1.x * w1 + v2.x * w2 + v3.x * w3;
            an1 += v0.y * w0 + v1.y * w1 + v2.y * w2 + v3.y * w3;
            an2 += v0.z * w0 + v1.z * w1 + v2.z * w2 + v3.z * w3;
            an3 += v0.w * w0 + v1.w * w1 + v2.w * w2 + v3.w * w3;
            ae0 += (u0.x + u1.x) + (u2.x + u3.x);
            ae1 += (u0.y + u1.y) + (u2.y + u3.y);
            ae2 += (u0.z + u1.z) + (u2.z + u3.z);
            ae3 += (u0.w + u1.w) + (u2.w + u3.w);

            q0 = p0; q1 = p1; q2 = p2; q3 = p3;
            i = nx;
        }
    }
    for (; i < cnt; i++) {
        int4 q0 = __ldcs(&g_rec[start + i]);
        float4 v0 = __ldg((const float4*)&nfeat[(size_t)q0.x * DD + c]);
        float4 u0 = __ldcs((const float4*)&efeat[(size_t)q0.z * DD + c]);
        float w0 = __int_as_float(q0.y);
        an0 += v0.x * w0; an1 += v0.y * w0; an2 += v0.z * w0; an3 += v0.w * w0;
        ae0 += u0.x; ae1 += u0.y; ae2 += u0.z; ae3 += u0.w;
    }

    float invd = 1.f / (float)(cnt + 1);
    float inve = (cnt > 0) ? 1.f / (float)cnt : 0.f;
    float xv[8] = {an0 * invd, an1 * invd, an2 * invd, an3 * invd,
                   ae0 * inve, ae1 * inve, ae2 * inve, ae3 * inve};

    // split to bf16 hi/lo; neigh part at k=c, edge part at k=128+c
    unsigned hp[4], lp[4];
#pragma unroll
    for (int p = 0; p < 4; p++) {
        __nv_bfloat16 h0 = __float2bfloat16_rn(xv[2 * p]);
        __nv_bfloat16 h1 = __float2bfloat16_rn(xv[2 * p + 1]);
        __nv_bfloat16 l0 = __float2bfloat16_rn(xv[2 * p] - __bfloat162float(h0));
        __nv_bfloat16 l1 = __float2bfloat16_rn(xv[2 * p + 1] - __bfloat162float(h1));
        hp[p] = pack_bf2(h0, h1);
        lp[p] = pack_bf2(l0, l1);
    }
    size_t base = (size_t)n * 256 + c;
    *(uint2*)&g_Xh[base]       = make_uint2(hp[0], hp[1]);
    *(uint2*)&g_Xh[base + 128] = make_uint2(hp[2], hp[3]);
    *(uint2*)&g_Xl[base]       = make_uint2(lp[0], lp[1]);
    *(uint2*)&g_Xl[base + 128] = make_uint2(lp[2], lp[3]);
}

// ---------------- K5: tensor-core GEMM, bf16x3 split, cp.async 2-stage ------
// out[100000,128] = Xh*Wh + Xh*Wl + Xl*Wh + bias ; CTA tile 128x128, K=256
// dynamic smem: 2 stages x 4 arrays x [128][40] bf16 = 81920 B
#define GPITCH 40
#define GSTAGE 20480  // elements per stage (4 * 128 * 40)
#define GARR   5120   // elements per array (128 * 40)

__global__ void __launch_bounds__(256, 2) k_gemm_tc(const float* __restrict__ bn,
                                                    const float* __restrict__ be,
                                                    float* __restrict__ out) {
    extern __shared__ __nv_bfloat16 smem[];
    int tid = threadIdx.x;
    int lane = tid & 31, wid = tid >> 5;
    int g = lane >> 2, t = lane & 3;
    int mw = (wid >> 1) * 32, nw = (wid & 1) * 64;
    int rowbase = blockIdx.x * 128;

    float acc[2][8][4];
#pragma unroll
    for (int mt = 0; mt < 2; mt++)
#pragma unroll
        for (int nt = 0; nt < 8; nt++)
#pragma unroll
            for (int p = 0; p < 4; p++) acc[mt][nt][p] = 0.f;

    // cp.async issue of k-tile kc into stage s
    auto issue = [&](int kc, int s) {
        __nv_bfloat16* Sxh = smem + s * GSTAGE;
        __nv_bfloat16* Sxl = Sxh + GARR;
        __nv_bfloat16* Swh = Sxl + GARR;
        __nv_bfloat16* Swl = Swh + GARR;
#pragma unroll
        for (int tt = 0; tt < 2; tt++) {
            int cc = tid + tt * 256;           // 0..511
            int row = cc >> 2, c16 = cc & 3;   // 16B chunk within 64B row-seg
            size_t gx = (size_t)(rowbase + row) * 256 + kc + c16 * 8;
            bool inb = (rowbase + row) < NN;
            cp16(&Sxh[row * GPITCH + c16 * 8], &g_Xh[gx], inb);
            cp16(&Sxl[row * GPITCH + c16 * 8], &g_Xl[gx], inb);
            size_t gw = (size_t)row * 256 + kc + c16 * 8;
            cp16(&Swh[row * GPITCH + c16 * 8], &g_Wh[gw], true);
            cp16(&Swl[row * GPITCH + c16 * 8], &g_Wl[gw], true);
        }
    };

    issue(0, 0);
    cp_commit();

    for (int it = 0; it < 8; it++) {
        if (it < 7) {
            issue((it + 1) * 32, (it + 1) & 1);
            cp_commit();
            cp_wait<1>();
        } else {
            cp_wait<0>();
        }
        __syncthreads();

        const __nv_bfloat16* Sxh = smem + (it & 1) * GSTAGE;
        const __nv_bfloat16* Sxl = Sxh + GARR;
        const __nv_bfloat16* Swh = Sxl + GARR;
        const __nv_bfloat16* Swl = Swh + GARR;

#pragma unroll
        for (int kk = 0; kk < 32; kk += 16) {
            unsigned ah[2][4], al[2][4];
#pragma unroll
            for (int mt = 0; mt < 2; mt++) {
                int rb = mw + mt * 16;
                ah[mt][0] = *(const unsigned*)&Sxh[(rb + g) * GPITCH + kk + t * 2];
                ah[mt][1] = *(const unsigned*)&Sxh[(rb + g + 8) * GPITCH + kk + t * 2];
                ah[mt][2] = *(const unsigned*)&Sxh[(rb + g) * GPITCH + kk + t * 2 + 8];
                ah[mt][3] = *(const unsigned*)&Sxh[(rb + g + 8) * GPITCH + kk + t * 2 + 8];
                al[mt][0] = *(const unsigned*)&Sxl[(rb + g) * GPITCH + kk + t * 2];
                al[mt][1] = *(const unsigned*)&Sxl[(rb + g + 8) * GPITCH + kk + t * 2];
                al[mt][2] = *(const unsigned*)&Sxl[(rb + g) * GPITCH + kk + t * 2 + 8];
                al[mt][3] = *(const unsigned*)&Sxl[(rb + g + 8) * GPITCH + kk + t * 2 + 8];
            }
#pragma unroll
            for (int nt = 0; nt < 8; nt++) {
                int nb = nw + nt * 8;
                unsigned bh0 = *(const unsigned*)&Swh[(nb + g) * GPITCH + kk + t * 2];
                unsigned bh1 = *(const unsigned*)&Swh[(nb + g) * GPITCH + kk + t * 2 + 8];
                unsigned bl0 = *(const unsigned*)&Swl[(nb + g) * GPITCH + kk + t * 2];
                unsigned bl1 = *(const unsigned*)&Swl[(nb + g) * GPITCH + kk + t * 2 + 8];
#pragma unroll
                for (int mt = 0; mt < 2; mt++) {
                    mma_bf16(acc[mt][nt], ah[mt][0], ah[mt][1], ah[mt][2], ah[mt][3], bh0, bh1);
                    mma_bf16(acc[mt][nt], ah[mt][0], ah[mt][1], ah[mt][2], ah[mt][3], bl0, bl1);
                    mma_bf16(acc[mt][nt], al[mt][0], al[mt][1], al[mt][2], al[mt][3], bh0, bh1);
                }
            }
        }
        __syncthreads();  // all threads done with this buffer before reissue
    }

    // epilogue: bias + deg-gated edge bias, streaming fp32 stores
#pragma unroll
    for (int nt = 0; nt < 8; nt++) {
        int col = nw + nt * 8 + t * 2;
        float bn0 = __ldg(&bn[col]), bn1 = __ldg(&bn[col + 1]);
        float be0 = __ldg(&be[col]), be1 = __ldg(&be[col + 1]);
#pragma unroll
        for (int mt = 0; mt < 2; mt++) {
            int m0 = rowbase + mw + mt * 16 + g;
            if (m0 < NN) {
                float f = (g_deg[m0] > 0) ? 1.f : 0.f;
                __stcs((float2*)&out[(size_t)m0 * DD + col],
                       make_float2(acc[mt][nt][0] + bn0 + f * be0,
                                   acc[mt][nt][1] + bn1 + f * be1));
            }
            int m1 = m0 + 8;
            if (m1 < NN) {
                float f = (g_deg[m1] > 0) ? 1.f : 0.f;
                __stcs((float2*)&out[(size_t)m1 * DD + col],
                       make_float2(acc[mt][nt][2] + bn0 + f * be0,
                                   acc[mt][nt][3] + bn1 + f * be1));
            }
        }
    }
}

// ---------------- launch ----------------------------------------------------
extern "C" void kernel_launch(void* const* d_in, const int* in_sizes, int n_in,
                              void* d_out, int out_size) {
    const float* nfeat = (const float*)d_in[0];
    const float* efeat = (const float*)d_in[1];
    const float* ew    = (const float*)d_in[2];
    const float* Wn    = (const float*)d_in[3];
    const float* bn    = (const float*)d_in[4];
    const float* We    = (const float*)d_in[5];
    const float* be    = (const float*)d_in[6];
    const int*   src   = (const int*)d_in[7];
    const int*   dst   = (const int*)d_in[8];
    float* out = (float*)d_out;

    const int nscan = (NN + 1023) / 1024;  // 98
    const int gemm_smem = 2 * 4 * 128 * GPITCH * (int)sizeof(__nv_bfloat16);  // 81920

    cudaFuncSetAttribute(k_gemm_tc, cudaFuncAttributeMaxDynamicSharedMemorySize, gemm_smem);

    k_init<<<400, 256>>>(Wn, We);
    k_deg<<<(NE + 255) / 256, 256>>>(dst);
    k_scan1<<<nscan, 1024>>>();
    k_addoff<<<nscan, 1024>>>();
    k_fill<<<(NE + 255) / 256, 256>>>(dst, src, ew);
    k_agg<<<(NN * 32 + 255) / 256, 256>>>(nfeat, efeat);
    k_gemm_tc<<<(NN + 127) / 128, 256, gemm_smem>>>(bn, be, out);
}